// round 3
// baseline (speedup 1.0000x reference)
#include <cuda_runtime.h>
#include <cstdint>

// SpikeFP64ExtractLow6: input x (N, 64) of {0,1} float32, output (N, 6) float32.
// e  = 11-bit int from cols 1..11 (col1 = MSB)
// s  = (e - 1023) mod 2048 = (e + 1025) & 0x7FF
// V  = 0b1 m0 m1 m2 m3 m4 m5   (m_i = col 12+i)
// out row (out[0] = MSB) = (s <= 5) ? (V >> (6 - s)) & 0x3F : 0
//
// Layout: 8 lanes per row, 4 rows per warp.
//   lanes sub=0..4 load float4 covering cols sub*4 .. sub*4+3  (bytes 0..79,
//   i.e. DRAM sectors 0,1,2 only — the needed bytes 4..71 live exactly there;
//   sector 3 and the second 128B line of each row are never touched)
//   -> per-row 32-bit presence mask assembled with 3 OR-shuffles
//   -> __brev gives both bit-reversed exponent and mantissa via shifts.

__global__ void __launch_bounds__(256) spike_fp64_extract_low6_kernel(
    const float4* __restrict__ x4,   // row stride = 16 float4
    float* __restrict__ out,
    int nrows)
{
    const int lane = threadIdx.x & 31;
    const int sub  = lane & 7;                 // position within 8-lane row group
    const int warp_global = (int)((blockIdx.x * blockDim.x + threadIdx.x) >> 5);
    const int row = warp_global * 4 + (lane >> 3);

    unsigned nib = 0u;
    if (row < nrows && sub < 5) {
        float4 v = __ldcs(&x4[(size_t)row * 16 + sub]);   // streaming: no reuse
        nib =  (unsigned)(v.x != 0.0f)
            | ((unsigned)(v.y != 0.0f) << 1)
            | ((unsigned)(v.z != 0.0f) << 2)
            | ((unsigned)(v.w != 0.0f) << 3);
    }

    // Per-row 32-bit mask: bit c = x[row][c] for c in 0..19 (cols 20..31 zero).
    // shfl_xor with 1,2,4 stays inside each 8-lane row group.
    unsigned mask = nib << (sub * 4);
    mask |= __shfl_xor_sync(0xffffffffu, mask, 1);
    mask |= __shfl_xor_sync(0xffffffffu, mask, 2);
    mask |= __shfl_xor_sync(0xffffffffu, mask, 4);

    // brev bit k = mask bit 31-k
    const unsigned br = __brev(mask);
    const unsigned e  = (br >> 20) & 0x7FFu;          // e bit i = x[11-i]
    const unsigned s  = (e + 1025u) & 0x7FFu;         // e - 1023 mod 2048
    const unsigned V  = ((br >> 14) & 0x3Fu) | 0x40u; // 1.m0m1m2m3m4m5
    const unsigned R  = (s <= 5u) ? (V >> (6u - s)) : 0u;

    // out[row*6 + j] = bit (5-j) of R ; lanes sub=0..5 each write one float.
    if (row < nrows && sub < 6) {
        __stcs(&out[(size_t)row * 6 + sub], (float)((R >> (5 - sub)) & 1u));
    }
}

extern "C" void kernel_launch(void* const* d_in, const int* in_sizes, int n_in,
                              void* d_out, int out_size)
{
    const float4* x4 = (const float4*)d_in[0];
    float* out = (float*)d_out;
    const int nrows = in_sizes[0] / 64;

    // 256 threads = 8 warps = 32 rows per block
    const int rows_per_block = 32;
    const int blocks = (nrows + rows_per_block - 1) / rows_per_block;
    spike_fp64_extract_low6_kernel<<<blocks, 256>>>(x4, out, nrows);
}

// round 14
// speedup vs baseline: 1.3141x; 1.3141x over previous
#include <cuda_runtime.h>
#include <cstdint>

// SpikeFP64ExtractLow6: input x (N, 64) of exact {0.0,1.0} float32,
// output (N, 6) float32.
//   e = 11-bit int from cols 1..11 (col1 = MSB)
//   s = (e + 1025) & 0x7FF            ( = (e - 1023) mod 2048 )
//   V = 0b1 m0..m5                    (m_i = col 12+i)
//   row bits (out[0] = MSB) = (s <= 5) ? (V >> (6 - s)) & 0x3F : 0
//
// One THREAD per row (round-3 8-lane layout was issue/ALU bound at 55% DRAM:
// 15 instrs/row; this is ~3/row). Coalesced global loads via smem staging
// (conflict-free: 80 B row stride = 20-bank stride, phases tile all banks);
// per-row compute uses FFMA Horner chains on the exact 0/1 floats (fma pipe
// was idle at 5.4%).

#define ROWS_PER_BLOCK 256

__global__ void __launch_bounds__(256) spike_fp64_extract_low6_kernel(
    const uint4* __restrict__ x4,    // row stride = 16 uint4 (256 B)
    float* __restrict__ out,
    int nrows)
{
    __shared__ uint4 srows[ROWS_PER_BLOCK * 5];   // 80 B per row (cols 0..19)

    const int t   = threadIdx.x;
    const int sub = t & 7;            // 0..7 within 8-lane load group
    const int rb  = t >> 3;           // 0..31
    const long long base_row = (long long)blockIdx.x * ROWS_PER_BLOCK;

    // ---- Stage 1: coalesced load, 8 independent LDG.128 per thread (MLP=8).
    // Each row needs bytes 4..71; the 5 uint4 (bytes 0..79) touch exactly
    // DRAM sectors 0..2 of the row's first 128B line.
#pragma unroll
    for (int i = 0; i < 8; i++) {
        const int r = i * 32 + rb;
        const long long row = base_row + r;
        if (sub < 5 && row < nrows)
            srows[r * 5 + sub] = __ldcs(&x4[row * 16 + sub]);
    }
    __syncthreads();

    // ---- Stage 2: one thread computes one full row.
    const long long row = base_row + t;
    if (row < nrows) {
        const uint4 q0 = srows[t * 5 + 0];   // cols 0..3
        const uint4 q1 = srows[t * 5 + 1];   // cols 4..7
        const uint4 q2 = srows[t * 5 + 2];   // cols 8..11
        const uint4 q3 = srows[t * 5 + 3];   // cols 12..15
        const uint4 q4 = srows[t * 5 + 4];   // cols 16..19

        // Horner chains on exact 0/1 floats (FFMA-imm, rt=1 on fma pipe).
        float e = __uint_as_float(q0.y);                   // col 1 (MSB)
        e = e * 2.0f + __uint_as_float(q0.z);              // col 2
        e = e * 2.0f + __uint_as_float(q0.w);              // col 3
        e = e * 2.0f + __uint_as_float(q1.x);              // col 4
        e = e * 2.0f + __uint_as_float(q1.y);              // col 5
        e = e * 2.0f + __uint_as_float(q1.z);              // col 6
        e = e * 2.0f + __uint_as_float(q1.w);              // col 7
        e = e * 2.0f + __uint_as_float(q2.x);              // col 8
        e = e * 2.0f + __uint_as_float(q2.y);              // col 9
        e = e * 2.0f + __uint_as_float(q2.z);              // col 10
        e = e * 2.0f + __uint_as_float(q2.w);              // col 11 (LSB)

        float vm = __uint_as_float(q3.x);                  // m0 (col 12)
        vm = vm * 2.0f + __uint_as_float(q3.y);            // m1
        vm = vm * 2.0f + __uint_as_float(q3.z);            // m2
        vm = vm * 2.0f + __uint_as_float(q3.w);            // m3
        vm = vm * 2.0f + __uint_as_float(q4.x);            // m4
        vm = vm * 2.0f + __uint_as_float(q4.y);            // m5 (col 17)

        const int      ei = (int)e;                        // exact integer
        const int      s  = (ei + 1025) & 2047;            // e - 1023 mod 2048
        const unsigned V  = (unsigned)(int)vm | 64u;       // 1.m0..m5
        const unsigned R  = (s <= 5) ? (V >> (6 - s)) : 0u;

        // bit -> float word without I2F: bit * 0x3F800000 (IMAD on fma pipe)
        uint2 o01, o23, o45;
        o01.x = ((R >> 5) & 1u) * 0x3F800000u;
        o01.y = ((R >> 4) & 1u) * 0x3F800000u;
        o23.x = ((R >> 3) & 1u) * 0x3F800000u;
        o23.y = ((R >> 2) & 1u) * 0x3F800000u;
        o45.x = ((R >> 1) & 1u) * 0x3F800000u;
        o45.y = ( R        & 1u) * 0x3F800000u;

        uint2* op = (uint2*)(out + row * 6);               // 24 B, 8-aligned
        __stcs(op + 0, o01);
        __stcs(op + 1, o23);
        __stcs(op + 2, o45);
    }
}

extern "C" void kernel_launch(void* const* d_in, const int* in_sizes, int n_in,
                              void* d_out, int out_size)
{
    const uint4* x4 = (const uint4*)d_in[0];
    float* out = (float*)d_out;
    const int nrows = in_sizes[0] / 64;

    const int blocks = (nrows + ROWS_PER_BLOCK - 1) / ROWS_PER_BLOCK;
    spike_fp64_extract_low6_kernel<<<blocks, 256>>>(x4, out, nrows);
}